// round 10
// baseline (speedup 1.0000x reference)
#include <cuda_runtime.h>

#define BB 64
#define SS 512
#define EE 512
#define HD 1024
#define NO 10
#define NBLK 128
#define GTHR 512

typedef unsigned long long ull;

// -------- scratch --------
__device__ float g_xproj[(size_t)SS * BB * 3 * HD]; // [s][b][3072]
__device__ float g_H[2][HD * BB];                   // k-major [k][b]
__device__ float g_Hr[2][HD * BB];                  // double-buffered by step parity
__device__ unsigned g_arrive[NBLK * 32];            // flat init barrier
__device__ unsigned g_F1[NBLK * 32];                // phase-1 done flags (step+1)
__device__ unsigned g_F2[NBLK * 32];                // phase-2 done flags (step+1)

// -------- packed f32x2 helpers --------
__device__ __forceinline__ ull ffma2(ull a, ull b, ull c) {
    ull d; asm("fma.rn.f32x2 %0, %1, %2, %3;" : "=l"(d) : "l"(a), "l"(b), "l"(c));
    return d;
}
__device__ __forceinline__ ull splat2(float x) {
    ull r; asm("mov.b64 %0, {%1,%1};" : "=l"(r) : "f"(x)); return r;
}
__device__ __forceinline__ float2 unpack2(ull v) {
    float2 f; asm("mov.b64 {%0,%1}, %2;" : "=f"(f.x), "=f"(f.y) : "l"(v)); return f;
}
__device__ __forceinline__ void ldcg_2x64(const float* p, ull& a, ull& b) {
    asm("ld.global.cg.v2.u64 {%0,%1}, [%2];" : "=l"(a), "=l"(b) : "l"(p));
}
__device__ __forceinline__ float2 ldcg_f2(const float* p) {
    float2 v; asm("ld.global.cg.v2.f32 {%0,%1}, [%2];" : "=f"(v.x), "=f"(v.y) : "l"(p));
    return v;
}
__device__ __forceinline__ float sigmoid_f(float x) {
    return 1.0f / (1.0f + __expf(-x));
}
__device__ __forceinline__ float tanh_f(float x) {
    float ax = fabsf(x);
    float t = __expf(-2.0f * ax);
    float r = __fdividef(1.0f - t, 1.0f + t);
    return copysignf(r, x);
}

// wait: lanes 0-7 poll the 8 producers of k-slice ks (relaxed spin, acquire confirm)
__device__ __forceinline__ void warp_wait_flags(const unsigned* F, int ks,
                                                unsigned target, int lane) {
    if (lane < 8) {
        const unsigned* p = F + (ks * 8 + lane) * 32;
        unsigned v;
        for (;;) {
            asm volatile("ld.relaxed.gpu.u32 %0, [%1];" : "=r"(v) : "l"(p) : "memory");
            if (v >= target) break;
            __nanosleep(20);
        }
        asm volatile("ld.acquire.gpu.u32 %0, [%1];" : "=r"(v) : "l"(p) : "memory");
    }
    __syncwarp();
}

__device__ __forceinline__ void publish(unsigned* slot, unsigned val) {
    asm volatile("st.release.gpu.u32 [%0], %1;" :: "l"(slot), "r"(val) : "memory");
}

// flat barrier (used once, after H0 init)
__device__ __forceinline__ void flat_barrier(unsigned target, int bx) {
    __syncthreads();
    if (threadIdx.x == 0) {
        __threadfence();
        publish(&g_arrive[bx * 32], target);
    }
    if (threadIdx.x < NBLK) {
        const unsigned* p = &g_arrive[threadIdx.x * 32];
        unsigned v;
        do {
            asm volatile("ld.acquire.gpu.u32 %0, [%1];" : "=r"(v) : "l"(p) : "memory");
        } while (v < target);
    }
    __syncthreads();
}

__global__ void reset_kernel() {
    int t = threadIdx.x;
    for (int i = t; i < NBLK * 32; i += blockDim.x) {
        g_arrive[i] = 0u; g_F1[i] = 0u; g_F2[i] = 0u;
    }
}

// =====================================================================
// Kernel 1: input projection. One block per s. A panel (64x512) staged
// fully in dynamic smem (row stride 68 floats = 272B, 16B-aligned);
// 48 col-tiles with double-buffered B (BK=32).
// =====================================================================
#define ASTRIDE 68
#define PROJ_SMEM ((512 * ASTRIDE + 2 * 32 * 64 + 64) * 4)

__global__ __launch_bounds__(256) void proj_kernel(
    const int* __restrict__ inputs, const float* __restrict__ emb,
    const float* __restrict__ Wxr, const float* __restrict__ Wxz,
    const float* __restrict__ Wxc, const float* __restrict__ br,
    const float* __restrict__ bz, const float* __restrict__ bc) {
    extern __shared__ float sm[];
    float* As = sm;                            // [k][ASTRIDE] (m 0..63)
    float* Bs = sm + 512 * ASTRIDE;            // [2][32][64]
    int*   tok = (int*)(sm + 512 * ASTRIDE + 2 * 32 * 64);

    const int s = blockIdx.x;
    const int tid = threadIdx.x;

    if (tid < 64) tok[tid] = inputs[tid * SS + s];
    __syncthreads();

    // stage entire A panel: 64 rows x 512 k (gathered from emb)
#pragma unroll 1
    for (int it = 0; it < 32; ++it) {
        int idx = tid + it * 256;              // 0..8191 float4s
        int row = idx >> 7;                    // 0..63
        int kq  = idx & 127;                   // float4 within row
        float4 av = __ldg((const float4*)(emb + (size_t)tok[row] * EE + kq * 4));
        As[(kq * 4 + 0) * ASTRIDE + row] = av.x;
        As[(kq * 4 + 1) * ASTRIDE + row] = av.y;
        As[(kq * 4 + 2) * ASTRIDE + row] = av.z;
        As[(kq * 4 + 3) * ASTRIDE + row] = av.w;
    }
    __syncthreads();

    const int tx = tid & 15, ty = tid >> 4;
    const int n0 = tx * 4, m0 = ty * 4;
    const int bk = tid >> 3;                   // 0..31 (B stage row)
    const int bn = (tid & 7) * 8;              // 0..56

#pragma unroll 1
    for (int ct = 0; ct < 48; ++ct) {
        const int gate = ct >> 4;
        const float* Wx   = (gate == 0) ? Wxr : ((gate == 1) ? Wxz : Wxc);
        const float* bias = (gate == 0) ? br  : ((gate == 1) ? bz  : bc);
        const int col0 = (ct & 15) * 64;

        // stage B chunk 0
        *(float4*)&Bs[0 * 2048 + bk * 64 + bn]     =
            *(const float4*)(Wx + (size_t)bk * HD + col0 + bn);
        *(float4*)&Bs[0 * 2048 + bk * 64 + bn + 4] =
            *(const float4*)(Wx + (size_t)bk * HD + col0 + bn + 4);
        __syncthreads();

        ull acc[4][2];
#pragma unroll
        for (int i = 0; i < 4; i++) { acc[i][0] = 0ull; acc[i][1] = 0ull; }

        int pb = 0;
#pragma unroll 1
        for (int k0 = 0; k0 < EE; k0 += 32) {
            float4 bva, bvb;
            const bool more = (k0 + 32 < EE);
            if (more) {
                bva = *(const float4*)(Wx + (size_t)(k0 + 32 + bk) * HD + col0 + bn);
                bvb = *(const float4*)(Wx + (size_t)(k0 + 32 + bk) * HD + col0 + bn + 4);
            }
#pragma unroll
            for (int kk = 0; kk < 32; ++kk) {
                float4 a4 = *(const float4*)&As[(k0 + kk) * ASTRIDE + m0];
                ulonglong2 b2 = *(const ulonglong2*)&Bs[pb * 2048 + kk * 64 + n0];
                ull aa;
                aa = splat2(a4.x);
                acc[0][0] = ffma2(aa, b2.x, acc[0][0]);
                acc[0][1] = ffma2(aa, b2.y, acc[0][1]);
                aa = splat2(a4.y);
                acc[1][0] = ffma2(aa, b2.x, acc[1][0]);
                acc[1][1] = ffma2(aa, b2.y, acc[1][1]);
                aa = splat2(a4.z);
                acc[2][0] = ffma2(aa, b2.x, acc[2][0]);
                acc[2][1] = ffma2(aa, b2.y, acc[2][1]);
                aa = splat2(a4.w);
                acc[3][0] = ffma2(aa, b2.x, acc[3][0]);
                acc[3][1] = ffma2(aa, b2.y, acc[3][1]);
            }
            if (more) {
                __syncthreads();
                *(float4*)&Bs[(pb ^ 1) * 2048 + bk * 64 + bn]     = bva;
                *(float4*)&Bs[(pb ^ 1) * 2048 + bk * 64 + bn + 4] = bvb;
                __syncthreads();
            }
            pb ^= 1;
        }
        float4 bi = *(const float4*)(bias + col0 + n0);
#pragma unroll
        for (int i = 0; i < 4; i++) {
            float2 lo = unpack2(acc[i][0]), hi = unpack2(acc[i][1]);
            float4 v = make_float4(lo.x + bi.x, lo.y + bi.y, hi.x + bi.z, hi.y + bi.w);
            __stcs((float4*)(g_xproj + ((size_t)s * BB + m0 + i) * (3 * HD) +
                             gate * HD + col0 + n0), v);
        }
        __syncthreads();
    }
}

// =====================================================================
// Kernel 2: persistent GRU, dataflow-synchronized, rotated k-slices.
// =====================================================================
__global__ __launch_bounds__(GTHR, 1) void gru_kernel(
    const float* __restrict__ Whr, const float* __restrict__ Whz,
    const float* __restrict__ Whc) {
    __shared__ ull red[8][512];
    __shared__ float xp1[64 * 18];
    __shared__ float xp2[64 * 10];
    __shared__ float zs[8 * 64];

    const int tid = threadIdx.x, bx = blockIdx.x;
    const int w = tid >> 5, lane = tid & 31;
    const int mg = lane & 7;
    const int cg = lane >> 3;
    const int ks = (w + bx) & 15;              // rotated k-slice for this warp

    // zero-init H0 every launch
    {
        int idx = bx * GTHR + tid;
        if (idx < HD * BB / 4)
            ((float4*)g_H[0])[idx] = make_float4(0.f, 0.f, 0.f, 0.f);
    }
    flat_barrier(1, bx);

    const int colb = bx * 8;
    const float* W1base = (cg < 2) ? Whr : Whz;
    const int w1col = colb + (cg & 1) * 4;

    const int e_el = tid & 31, e_q = tid >> 5;
    const int e1_i = e_q >> 2, e1_j = e_q & 3;
    const int e1_row = (e_el & 7) * 4 + e1_i;
    const int e1_col = (e_el >> 3) * 4 + e1_j;     // 0..15 (0-7 r, 8-15 z)
    const int e1_mb = 2 * e1_row;
    const int e2_i = e_q >> 1, e2_j = e_q & 1;
    const int e2_row = (e_el & 7) * 4 + e2_i;
    const int e2_col = (e_el >> 3) * 2 + e2_j;     // 0..7
    const int e2_mb = 2 * e2_row;

    int p = 0;
#pragma unroll 1
    for (int s = 0; s < SS; ++s) {
        const float* Hc = g_H[p];
        float* Hn = g_H[p ^ 1];
        float* Hrbuf = g_Hr[s & 1];
        const float* xpg = g_xproj + (size_t)s * BB * 3 * HD;

        // prefetches (own-column data: self-produced or independent)
        float2 xv1, xv2;
        {
            int b = tid >> 3, c2 = (tid & 7) * 2;
            const float* src = (c2 < 8)
                ? xpg + b * 3 * HD + 0 * HD + colb + c2
                : xpg + b * 3 * HD + 1 * HD + colb + (c2 - 8);
            xv1 = __ldcs((const float2*)src);
        }
        if (tid < 256) {
            int b = tid >> 2, q = tid & 3;
            xv2 = __ldcs((const float2*)(xpg + b * 3 * HD + 2 * HD + colb + q * 2));
        }
        float2 hc1, hc2;
        if (e1_col < 8) hc1 = ldcg_f2(Hc + (colb + e1_col) * BB + e1_mb);
        if (tid < 256)  hc2 = ldcg_f2(Hc + (colb + e2_col) * BB + e2_mb);

        // wait for producers of my rotated H slice (phase-2 of step s-1)
        warp_wait_flags(g_F2, ks, (unsigned)s, lane);

        // ---------------- phase 1: r and z ----------------
        ull acc[4][4];
#pragma unroll
        for (int i = 0; i < 4; i++)
#pragma unroll
            for (int j = 0; j < 4; j++) acc[i][j] = 0ull;
        {
            const float* hptr = Hc + (ks * 64) * BB + mg * 8;
            const float* wptr = W1base + (size_t)(ks * 64) * HD + w1col;
#pragma unroll 1
            for (int k = 0; k < 64; k += 8) {
#pragma unroll
                for (int u = 0; u < 8; ++u) {
                    ull h0, h1, h2, h3;
                    ldcg_2x64(hptr, h0, h1);
                    ldcg_2x64(hptr + 4, h2, h3);
                    float4 wv = __ldg((const float4*)wptr);
                    ull w0 = splat2(wv.x), w1 = splat2(wv.y);
                    ull w2 = splat2(wv.z), w3 = splat2(wv.w);
                    acc[0][0] = ffma2(h0, w0, acc[0][0]);
                    acc[0][1] = ffma2(h0, w1, acc[0][1]);
                    acc[0][2] = ffma2(h0, w2, acc[0][2]);
                    acc[0][3] = ffma2(h0, w3, acc[0][3]);
                    acc[1][0] = ffma2(h1, w0, acc[1][0]);
                    acc[1][1] = ffma2(h1, w1, acc[1][1]);
                    acc[1][2] = ffma2(h1, w2, acc[1][2]);
                    acc[1][3] = ffma2(h1, w3, acc[1][3]);
                    acc[2][0] = ffma2(h2, w0, acc[2][0]);
                    acc[2][1] = ffma2(h2, w1, acc[2][1]);
                    acc[2][2] = ffma2(h2, w2, acc[2][2]);
                    acc[2][3] = ffma2(h2, w3, acc[2][3]);
                    acc[3][0] = ffma2(h3, w0, acc[3][0]);
                    acc[3][1] = ffma2(h3, w1, acc[3][1]);
                    acc[3][2] = ffma2(h3, w2, acc[3][2]);
                    acc[3][3] = ffma2(h3, w3, acc[3][3]);
                    hptr += BB; wptr += HD;
                }
            }
        }
        if (w < 8) {
#pragma unroll
            for (int i = 0; i < 4; i++)
#pragma unroll
                for (int j = 0; j < 4; j++)
                    red[w][(i * 4 + j) * 32 + lane] = acc[i][j];
        }
        {
            int b = tid >> 3, c2 = (tid & 7) * 2;
            *(float2*)&xp1[b * 18 + c2] = xv1;
        }
        if (tid < 256) {
            int b = tid >> 2, q = tid & 3;
            *(float2*)&xp2[b * 10 + q * 2] = xv2;
        }
        __syncthreads();
        if (w >= 8) {
#pragma unroll
            for (int i = 0; i < 4; i++)
#pragma unroll
                for (int j = 0; j < 4; j++) {
                    int slot = (i * 4 + j) * 32 + lane;
                    float2 a = unpack2(acc[i][j]);
                    float2 c = unpack2(red[w - 8][slot]);
                    a.x += c.x; a.y += c.y;
                    red[w - 8][slot] = *(ull*)&a;
                }
        }
        __syncthreads();

        {
            float2 sum = make_float2(0.f, 0.f);
#pragma unroll
            for (int ww = 0; ww < 8; ++ww) {
                float2 v = unpack2(red[ww][tid]);
                sum.x += v.x; sum.y += v.y;
            }
            float v0 = sigmoid_f(sum.x + xp1[e1_mb * 18 + e1_col]);
            float v1 = sigmoid_f(sum.y + xp1[(e1_mb + 1) * 18 + e1_col]);
            if (e1_col < 8) {
                *(float2*)(Hrbuf + (colb + e1_col) * BB + e1_mb) =
                    make_float2(hc1.x * v0, hc1.y * v1);
            } else {
                *(float2*)&zs[(e1_col - 8) * 64 + e1_mb] = make_float2(v0, v1);
            }
        }
        __syncthreads();
        if (tid == 0) {
            __threadfence();
            publish(&g_F1[bx * 32], (unsigned)(s + 1));
        }

        // wait for producers of my rotated Hr slice (phase-1 of step s)
        warp_wait_flags(g_F1, ks, (unsigned)(s + 1), lane);

        // ---------------- phase 2: candidate h ----------------
        ull acc2[4][2];
#pragma unroll
        for (int i = 0; i < 4; i++) { acc2[i][0] = 0ull; acc2[i][1] = 0ull; }
        {
            const float* hptr = Hrbuf + (ks * 64) * BB + mg * 8;
            const float* wptr = Whc + (size_t)(ks * 64) * HD + colb + cg * 2;
#pragma unroll 1
            for (int k = 0; k < 64; k += 8) {
#pragma unroll
                for (int u = 0; u < 8; ++u) {
                    ull h0, h1, h2, h3;
                    ldcg_2x64(hptr, h0, h1);
                    ldcg_2x64(hptr + 4, h2, h3);
                    float2 wv = __ldg((const float2*)wptr);
                    ull w0 = splat2(wv.x), w1 = splat2(wv.y);
                    acc2[0][0] = ffma2(h0, w0, acc2[0][0]);
                    acc2[0][1] = ffma2(h0, w1, acc2[0][1]);
                    acc2[1][0] = ffma2(h1, w0, acc2[1][0]);
                    acc2[1][1] = ffma2(h1, w1, acc2[1][1]);
                    acc2[2][0] = ffma2(h2, w0, acc2[2][0]);
                    acc2[2][1] = ffma2(h2, w1, acc2[2][1]);
                    acc2[3][0] = ffma2(h3, w0, acc2[3][0]);
                    acc2[3][1] = ffma2(h3, w1, acc2[3][1]);
                    hptr += BB; wptr += HD;
                }
            }
        }
        if (w < 8) {
#pragma unroll
            for (int i = 0; i < 4; i++)
#pragma unroll
                for (int j = 0; j < 2; j++)
                    red[w][(i * 2 + j) * 32 + lane] = acc2[i][j];
        }
        __syncthreads();
        if (w >= 8) {
#pragma unroll
            for (int i = 0; i < 4; i++)
#pragma unroll
                for (int j = 0; j < 2; j++) {
                    int slot = (i * 2 + j) * 32 + lane;
                    float2 a = unpack2(acc2[i][j]);
                    float2 c = unpack2(red[w - 8][slot]);
                    a.x += c.x; a.y += c.y;
                    red[w - 8][slot] = *(ull*)&a;
                }
        }
        __syncthreads();

        if (tid < 256) {
            float2 sum = make_float2(0.f, 0.f);
#pragma unroll
            for (int ww = 0; ww < 8; ++ww) {
                float2 v = unpack2(red[ww][tid]);
                sum.x += v.x; sum.y += v.y;
            }
            float h0 = tanh_f(sum.x + xp2[e2_mb * 10 + e2_col]);
            float h1 = tanh_f(sum.y + xp2[(e2_mb + 1) * 10 + e2_col]);
            float2 z = *(const float2*)&zs[e2_col * 64 + e2_mb];
            *(float2*)(Hn + (colb + e2_col) * BB + e2_mb) =
                make_float2(z.x * hc2.x + (1.f - z.x) * h0,
                            z.y * hc2.y + (1.f - z.y) * h1);
        }
        __syncthreads();
        if (tid == 0) {
            __threadfence();
            publish(&g_F2[bx * 32], (unsigned)(s + 1));
        }
        p ^= 1;
    }
}

// =====================================================================
// Kernel 3: logits + softmax
// =====================================================================
__global__ __launch_bounds__(256) void out_kernel(const float* __restrict__ Whq,
                                                  const float* __restrict__ bq,
                                                  float* __restrict__ out) {
    const int b = blockIdx.x;
    const int t = threadIdx.x;
    float acc[NO];
#pragma unroll
    for (int o = 0; o < NO; o++) acc[o] = 0.f;
#pragma unroll
    for (int i = 0; i < HD / 256; i++) {
        int k = t + i * 256;
        float hv = g_H[0][k * BB + b];
        const float* wp = Whq + (size_t)k * NO;
#pragma unroll
        for (int o = 0; o < NO; o++) acc[o] += hv * wp[o];
    }
    __shared__ float part[256 * NO];
#pragma unroll
    for (int o = 0; o < NO; o++) part[t * NO + o] = acc[o];
    __syncthreads();
    __shared__ float logits[NO];
    if (t < NO) {
        float sum = bq[t];
        for (int i = 0; i < 256; i++) sum += part[i * NO + t];
        logits[t] = sum;
    }
    __syncthreads();
    if (t == 0) {
        float mx = logits[0];
#pragma unroll
        for (int o = 1; o < NO; o++) mx = fmaxf(mx, logits[o]);
        float e[NO]; float sum = 0.f;
#pragma unroll
        for (int o = 0; o < NO; o++) { e[o] = __expf(logits[o] - mx); sum += e[o]; }
        float inv = 1.0f / sum;
#pragma unroll
        for (int o = 0; o < NO; o++) out[b * NO + o] = e[o] * inv;
    }
}

// =====================================================================
extern "C" void kernel_launch(void* const* d_in, const int* in_sizes, int n_in,
                              void* d_out, int out_size) {
    const int*   inputs = (const int*)d_in[0];
    const float* emb = (const float*)d_in[1];
    const float* Wxr = (const float*)d_in[2];
    const float* Whr = (const float*)d_in[3];
    const float* br  = (const float*)d_in[4];
    const float* Wxz = (const float*)d_in[5];
    const float* Whz = (const float*)d_in[6];
    const float* bz  = (const float*)d_in[7];
    const float* Wxc = (const float*)d_in[8];
    const float* Whc = (const float*)d_in[9];
    const float* bc  = (const float*)d_in[10];
    const float* Whq = (const float*)d_in[11];
    const float* bq  = (const float*)d_in[12];
    float* out = (float*)d_out;

    static int smem_set = 0;
    if (!smem_set) {
        cudaFuncSetAttribute(proj_kernel,
                             cudaFuncAttributeMaxDynamicSharedMemorySize, PROJ_SMEM);
        smem_set = 1;
    }

    reset_kernel<<<1, 256>>>();
    proj_kernel<<<512, 256, PROJ_SMEM>>>(inputs, emb, Wxr, Wxz, Wxc, br, bz, bc);
    gru_kernel<<<NBLK, GTHR>>>(Whr, Whz, Whc);
    out_kernel<<<64, 256>>>(Whq, bq, out);
}

// round 11
// speedup vs baseline: 1.0458x; 1.0458x over previous
#include <cuda_runtime.h>

#define BB 64
#define SS 512
#define EE 512
#define HD 1024
#define NO 10
#define NBLK 128
#define GTHR 512

typedef unsigned long long ull;

// -------- scratch --------
__device__ float g_xproj[(size_t)SS * BB * 3 * HD]; // [s][b][3072]
__device__ float g_H[2][HD * BB];                   // k-major [k][b]
__device__ float g_Hr[2][HD * BB];                  // double-buffered by step parity
__device__ unsigned g_arrive[NBLK * 32];            // flat init barrier
__device__ unsigned g_F1[NBLK * 32];                // phase-1 done flags (step+1)
__device__ unsigned g_F2[NBLK * 32];                // phase-2 done flags (step+1)

// -------- packed f32x2 helpers --------
__device__ __forceinline__ ull ffma2(ull a, ull b, ull c) {
    ull d; asm("fma.rn.f32x2 %0, %1, %2, %3;" : "=l"(d) : "l"(a), "l"(b), "l"(c));
    return d;
}
__device__ __forceinline__ ull splat2(float x) {
    ull r; asm("mov.b64 %0, {%1,%1};" : "=l"(r) : "f"(x)); return r;
}
__device__ __forceinline__ float2 unpack2(ull v) {
    float2 f; asm("mov.b64 {%0,%1}, %2;" : "=f"(f.x), "=f"(f.y) : "l"(v)); return f;
}
__device__ __forceinline__ void ldcg_2x64(const float* p, ull& a, ull& b) {
    asm("ld.global.cg.v2.u64 {%0,%1}, [%2];" : "=l"(a), "=l"(b) : "l"(p));
}
__device__ __forceinline__ float2 ldcg_f2(const float* p) {
    float2 v; asm("ld.global.cg.v2.f32 {%0,%1}, [%2];" : "=f"(v.x), "=f"(v.y) : "l"(p));
    return v;
}
__device__ __forceinline__ float sigmoid_f(float x) {
    return 1.0f / (1.0f + __expf(-x));
}
__device__ __forceinline__ float tanh_f(float x) {
    float ax = fabsf(x);
    float t = __expf(-2.0f * ax);
    float r = __fdividef(1.0f - t, 1.0f + t);
    return copysignf(r, x);
}

// wait: lanes 0-7 poll the 8 producers of k-slice ks (relaxed spin, acquire confirm)
__device__ __forceinline__ void warp_wait_flags(const unsigned* F, int ks,
                                                unsigned target, int lane) {
    if (lane < 8) {
        const unsigned* p = F + (ks * 8 + lane) * 32;
        unsigned v;
        for (;;) {
            asm volatile("ld.relaxed.gpu.u32 %0, [%1];" : "=r"(v) : "l"(p) : "memory");
            if (v >= target) break;
            __nanosleep(20);
        }
        asm volatile("ld.acquire.gpu.u32 %0, [%1];" : "=r"(v) : "l"(p) : "memory");
    }
    __syncwarp();
}

__device__ __forceinline__ void publish(unsigned* slot, unsigned val) {
    asm volatile("st.release.gpu.u32 [%0], %1;" :: "l"(slot), "r"(val) : "memory");
}

// flat barrier (used once, after H0 init)
__device__ __forceinline__ void flat_barrier(unsigned target, int bx) {
    __syncthreads();
    if (threadIdx.x == 0) {
        __threadfence();
        publish(&g_arrive[bx * 32], target);
    }
    if (threadIdx.x < NBLK) {
        const unsigned* p = &g_arrive[threadIdx.x * 32];
        unsigned v;
        do {
            asm volatile("ld.acquire.gpu.u32 %0, [%1];" : "=r"(v) : "l"(p) : "memory");
        } while (v < target);
    }
    __syncthreads();
}

__global__ void reset_kernel() {
    int t = threadIdx.x;
    for (int i = t; i < NBLK * 32; i += blockDim.x) {
        g_arrive[i] = 0u; g_F1[i] = 0u; g_F2[i] = 0u;
    }
}

// =====================================================================
// Kernel 1: input projection, double-buffered smem (R8 version)
// =====================================================================
__global__ __launch_bounds__(256) void proj_kernel(
    const int* __restrict__ inputs, const float* __restrict__ emb,
    const float* __restrict__ Wxr, const float* __restrict__ Wxz,
    const float* __restrict__ Wxc, const float* __restrict__ br,
    const float* __restrict__ bz, const float* __restrict__ bc) {
    const int s  = blockIdx.y;
    const int nt = blockIdx.x;
    const int gate = nt >> 4;
    const float* Wx   = (gate == 0) ? Wxr : ((gate == 1) ? Wxz : Wxc);
    const float* bias = (gate == 0) ? br  : ((gate == 1) ? bz  : bc);
    const int col0 = (nt & 15) * 64;

    __shared__ int tok[64];
    __shared__ __align__(16) float As[2][16][68];
    __shared__ __align__(16) float Bs[2][16][64];

    const int tid = threadIdx.x;
    if (tid < 64) tok[tid] = inputs[tid * SS + s];
    __syncthreads();

    const int tx = tid & 15, ty = tid >> 4;
    const int n0 = tx * 4, m0 = ty * 4;
    ull acc[4][2];
#pragma unroll
    for (int i = 0; i < 4; i++) { acc[i][0] = 0ull; acc[i][1] = 0ull; }

    const int lm = tid >> 2, lkq = tid & 3;
    const int bk = tid >> 4, bnq = tid & 15;

    const float* eptr = emb + (size_t)tok[lm] * EE + lkq * 4;
    {
        float4 av = *(const float4*)(eptr);
        float4 bv = *(const float4*)(Wx + (size_t)bk * HD + col0 + bnq * 4);
        As[0][lkq * 4 + 0][lm] = av.x;
        As[0][lkq * 4 + 1][lm] = av.y;
        As[0][lkq * 4 + 2][lm] = av.z;
        As[0][lkq * 4 + 3][lm] = av.w;
        *(float4*)&Bs[0][bk][bnq * 4] = bv;
    }
    __syncthreads();

    int p = 0;
#pragma unroll 1
    for (int k0 = 0; k0 < EE; k0 += 16) {
        float4 av_n, bv_n;
        const bool more = (k0 + 16 < EE);
        if (more) {
            av_n = *(const float4*)(eptr + k0 + 16);
            bv_n = *(const float4*)(Wx + (size_t)(k0 + 16 + bk) * HD + col0 + bnq * 4);
        }
#pragma unroll
        for (int kk = 0; kk < 16; ++kk) {
            float4 a4 = *(const float4*)&As[p][kk][m0];
            ulonglong2 b2 = *(const ulonglong2*)&Bs[p][kk][n0];
            ull aa;
            aa = splat2(a4.x);
            acc[0][0] = ffma2(aa, b2.x, acc[0][0]);
            acc[0][1] = ffma2(aa, b2.y, acc[0][1]);
            aa = splat2(a4.y);
            acc[1][0] = ffma2(aa, b2.x, acc[1][0]);
            acc[1][1] = ffma2(aa, b2.y, acc[1][1]);
            aa = splat2(a4.z);
            acc[2][0] = ffma2(aa, b2.x, acc[2][0]);
            acc[2][1] = ffma2(aa, b2.y, acc[2][1]);
            aa = splat2(a4.w);
            acc[3][0] = ffma2(aa, b2.x, acc[3][0]);
            acc[3][1] = ffma2(aa, b2.y, acc[3][1]);
        }
        if (more) {
            As[p ^ 1][lkq * 4 + 0][lm] = av_n.x;
            As[p ^ 1][lkq * 4 + 1][lm] = av_n.y;
            As[p ^ 1][lkq * 4 + 2][lm] = av_n.z;
            As[p ^ 1][lkq * 4 + 3][lm] = av_n.w;
            *(float4*)&Bs[p ^ 1][bk][bnq * 4] = bv_n;
            __syncthreads();
        }
        p ^= 1;
    }
    float4 bi = *(const float4*)(bias + col0 + n0);
#pragma unroll
    for (int i = 0; i < 4; i++) {
        float2 lo = unpack2(acc[i][0]), hi = unpack2(acc[i][1]);
        float4 v = make_float4(lo.x + bi.x, lo.y + bi.y, hi.x + bi.z, hi.y + bi.w);
        __stcs((float4*)(g_xproj + ((size_t)s * BB + m0 + i) * (3 * HD) + gate * HD + col0 + n0), v);
    }
}

// =====================================================================
// Kernel 2: persistent GRU (R8 base), single-stage 16-warp reduction
// via dynamic smem. 128 blocks x 512 threads. ks = w (no rotation).
// =====================================================================
// dynamic smem layout (floats):
//   red : 16 warps * 512 ull slots  -> 16*512*2 = 16384 floats (64 KB)
//   xp1 : 64*18 = 1152
//   xp2 : 64*10 = 640
//   zs  : 8*64  = 512
#define RED_F   (16 * 512 * 2)
#define XP1_F   (64 * 18)
#define XP2_F   (64 * 10)
#define ZS_F    (8 * 64)
#define GRU_SMEM ((RED_F + XP1_F + XP2_F + ZS_F) * 4)

__global__ __launch_bounds__(GTHR, 1) void gru_kernel(
    const float* __restrict__ Whr, const float* __restrict__ Whz,
    const float* __restrict__ Whc) {
    extern __shared__ __align__(16) float smf[];
    ull*   red = (ull*)smf;                       // [16][512]
    float* xp1 = smf + RED_F;
    float* xp2 = smf + RED_F + XP1_F;
    float* zs  = smf + RED_F + XP1_F + XP2_F;

    const int tid = threadIdx.x, bx = blockIdx.x;
    const int w = tid >> 5, lane = tid & 31;
    const int mg = lane & 7;
    const int cg = lane >> 3;

    // zero-init H0 every launch
    {
        int idx = bx * GTHR + tid;
        if (idx < HD * BB / 4)
            ((float4*)g_H[0])[idx] = make_float4(0.f, 0.f, 0.f, 0.f);
    }
    flat_barrier(1, bx);

    const int colb = bx * 8;
    const float* W1base = (cg < 2) ? Whr : Whz;
    const int w1col = colb + (cg & 1) * 4;

    const int e_el = tid & 31, e_q = tid >> 5;
    const int e1_i = e_q >> 2, e1_j = e_q & 3;
    const int e1_row = (e_el & 7) * 4 + e1_i;
    const int e1_col = (e_el >> 3) * 4 + e1_j;     // 0..15 (0-7 r, 8-15 z)
    const int e1_mb = 2 * e1_row;
    const int e2_i = e_q >> 1, e2_j = e_q & 1;
    const int e2_row = (e_el & 7) * 4 + e2_i;
    const int e2_col = (e_el >> 3) * 2 + e2_j;     // 0..7
    const int e2_mb = 2 * e2_row;

    int p = 0;
#pragma unroll 1
    for (int s = 0; s < SS; ++s) {
        const float* Hc = g_H[p];
        float* Hn = g_H[p ^ 1];
        float* Hrbuf = g_Hr[s & 1];
        const float* xpg = g_xproj + (size_t)s * BB * 3 * HD;

        // prefetches (own-column data: self-produced or independent)
        float2 xv1, xv2;
        {
            int b = tid >> 3, c2 = (tid & 7) * 2;
            const float* src = (c2 < 8)
                ? xpg + b * 3 * HD + 0 * HD + colb + c2
                : xpg + b * 3 * HD + 1 * HD + colb + (c2 - 8);
            xv1 = __ldcs((const float2*)src);
        }
        if (tid < 256) {
            int b = tid >> 2, q = tid & 3;
            xv2 = __ldcs((const float2*)(xpg + b * 3 * HD + 2 * HD + colb + q * 2));
        }
        float2 hc1, hc2;
        if (e1_col < 8) hc1 = ldcg_f2(Hc + (colb + e1_col) * BB + e1_mb);
        if (tid < 256)  hc2 = ldcg_f2(Hc + (colb + e2_col) * BB + e2_mb);

        // wait for producers of my H slice (phase-2 of step s-1)
        warp_wait_flags(g_F2, w, (unsigned)s, lane);

        // ---------------- phase 1: r and z ----------------
        ull acc[4][4];
#pragma unroll
        for (int i = 0; i < 4; i++)
#pragma unroll
            for (int j = 0; j < 4; j++) acc[i][j] = 0ull;
        {
            const float* hptr = Hc + (w * 64) * BB + mg * 8;
            const float* wptr = W1base + (size_t)(w * 64) * HD + w1col;
#pragma unroll 1
            for (int k = 0; k < 64; k += 8) {
#pragma unroll
                for (int u = 0; u < 8; ++u) {
                    ull h0, h1, h2, h3;
                    ldcg_2x64(hptr, h0, h1);
                    ldcg_2x64(hptr + 4, h2, h3);
                    float4 wv = __ldg((const float4*)wptr);
                    ull w0 = splat2(wv.x), w1 = splat2(wv.y);
                    ull w2 = splat2(wv.z), w3 = splat2(wv.w);
                    acc[0][0] = ffma2(h0, w0, acc[0][0]);
                    acc[0][1] = ffma2(h0, w1, acc[0][1]);
                    acc[0][2] = ffma2(h0, w2, acc[0][2]);
                    acc[0][3] = ffma2(h0, w3, acc[0][3]);
                    acc[1][0] = ffma2(h1, w0, acc[1][0]);
                    acc[1][1] = ffma2(h1, w1, acc[1][1]);
                    acc[1][2] = ffma2(h1, w2, acc[1][2]);
                    acc[1][3] = ffma2(h1, w3, acc[1][3]);
                    acc[2][0] = ffma2(h2, w0, acc[2][0]);
                    acc[2][1] = ffma2(h2, w1, acc[2][1]);
                    acc[2][2] = ffma2(h2, w2, acc[2][2]);
                    acc[2][3] = ffma2(h2, w3, acc[2][3]);
                    acc[3][0] = ffma2(h3, w0, acc[3][0]);
                    acc[3][1] = ffma2(h3, w1, acc[3][1]);
                    acc[3][2] = ffma2(h3, w2, acc[3][2]);
                    acc[3][3] = ffma2(h3, w3, acc[3][3]);
                    hptr += BB; wptr += HD;
                }
            }
        }
        // single-stage: every warp stores its 16 partials (lane-linear)
#pragma unroll
        for (int i = 0; i < 4; i++)
#pragma unroll
            for (int j = 0; j < 4; j++)
                red[w * 512 + (i * 4 + j) * 32 + lane] = acc[i][j];
        {
            int b = tid >> 3, c2 = (tid & 7) * 2;
            *(float2*)&xp1[b * 18 + c2] = xv1;
        }
        if (tid < 256) {
            int b = tid >> 2, q = tid & 3;
            *(float2*)&xp2[b * 10 + q * 2] = xv2;
        }
        __syncthreads();

        // epilogue: thread t sums all 16 warps at slot t
        {
            float2 sum = make_float2(0.f, 0.f);
#pragma unroll
            for (int ww = 0; ww < 16; ++ww) {
                float2 v = unpack2(red[ww * 512 + tid]);
                sum.x += v.x; sum.y += v.y;
            }
            float v0 = sigmoid_f(sum.x + xp1[e1_mb * 18 + e1_col]);
            float v1 = sigmoid_f(sum.y + xp1[(e1_mb + 1) * 18 + e1_col]);
            if (e1_col < 8) {
                *(float2*)(Hrbuf + (colb + e1_col) * BB + e1_mb) =
                    make_float2(hc1.x * v0, hc1.y * v1);
            } else {
                *(float2*)&zs[(e1_col - 8) * 64 + e1_mb] = make_float2(v0, v1);
            }
        }
        __syncthreads();
        if (tid == 0) {
            __threadfence();
            publish(&g_F1[bx * 32], (unsigned)(s + 1));
        }

        // wait for producers of my Hr slice (phase-1 of step s)
        warp_wait_flags(g_F1, w, (unsigned)(s + 1), lane);

        // ---------------- phase 2: candidate h ----------------
        ull acc2[4][2];
#pragma unroll
        for (int i = 0; i < 4; i++) { acc2[i][0] = 0ull; acc2[i][1] = 0ull; }
        {
            const float* hptr = Hrbuf + (w * 64) * BB + mg * 8;
            const float* wptr = Whc + (size_t)(w * 64) * HD + colb + cg * 2;
#pragma unroll 1
            for (int k = 0; k < 64; k += 8) {
#pragma unroll
                for (int u = 0; u < 8; ++u) {
                    ull h0, h1, h2, h3;
                    ldcg_2x64(hptr, h0, h1);
                    ldcg_2x64(hptr + 4, h2, h3);
                    float2 wv = __ldg((const float2*)wptr);
                    ull w0 = splat2(wv.x), w1 = splat2(wv.y);
                    acc2[0][0] = ffma2(h0, w0, acc2[0][0]);
                    acc2[0][1] = ffma2(h0, w1, acc2[0][1]);
                    acc2[1][0] = ffma2(h1, w0, acc2[1][0]);
                    acc2[1][1] = ffma2(h1, w1, acc2[1][1]);
                    acc2[2][0] = ffma2(h2, w0, acc2[2][0]);
                    acc2[2][1] = ffma2(h2, w1, acc2[2][1]);
                    acc2[3][0] = ffma2(h3, w0, acc2[3][0]);
                    acc2[3][1] = ffma2(h3, w1, acc2[3][1]);
                    hptr += BB; wptr += HD;
                }
            }
        }
#pragma unroll
        for (int i = 0; i < 4; i++)
#pragma unroll
            for (int j = 0; j < 2; j++)
                red[w * 512 + (i * 2 + j) * 32 + lane] = acc2[i][j];
        __syncthreads();

        if (tid < 256) {
            float2 sum = make_float2(0.f, 0.f);
#pragma unroll
            for (int ww = 0; ww < 16; ++ww) {
                float2 v = unpack2(red[ww * 512 + tid]);
                sum.x += v.x; sum.y += v.y;
            }
            float h0 = tanh_f(sum.x + xp2[e2_mb * 10 + e2_col]);
            float h1 = tanh_f(sum.y + xp2[(e2_mb + 1) * 10 + e2_col]);
            float2 z = *(const float2*)&zs[e2_col * 64 + e2_mb];
            *(float2*)(Hn + (colb + e2_col) * BB + e2_mb) =
                make_float2(z.x * hc2.x + (1.f - z.x) * h0,
                            z.y * hc2.y + (1.f - z.y) * h1);
        }
        __syncthreads();
        if (tid == 0) {
            __threadfence();
            publish(&g_F2[bx * 32], (unsigned)(s + 1));
        }
        p ^= 1;
    }
}

// =====================================================================
// Kernel 3: logits + softmax
// =====================================================================
__global__ __launch_bounds__(256) void out_kernel(const float* __restrict__ Whq,
                                                  const float* __restrict__ bq,
                                                  float* __restrict__ out) {
    const int b = blockIdx.x;
    const int t = threadIdx.x;
    float acc[NO];
#pragma unroll
    for (int o = 0; o < NO; o++) acc[o] = 0.f;
#pragma unroll
    for (int i = 0; i < HD / 256; i++) {
        int k = t + i * 256;
        float hv = g_H[0][k * BB + b];
        const float* wp = Whq + (size_t)k * NO;
#pragma unroll
        for (int o = 0; o < NO; o++) acc[o] += hv * wp[o];
    }
    __shared__ float part[256 * NO];
#pragma unroll
    for (int o = 0; o < NO; o++) part[t * NO + o] = acc[o];
    __syncthreads();
    __shared__ float logits[NO];
    if (t < NO) {
        float sum = bq[t];
        for (int i = 0; i < 256; i++) sum += part[i * NO + t];
        logits[t] = sum;
    }
    __syncthreads();
    if (t == 0) {
        float mx = logits[0];
#pragma unroll
        for (int o = 1; o < NO; o++) mx = fmaxf(mx, logits[o]);
        float e[NO]; float sum = 0.f;
#pragma unroll
        for (int o = 0; o < NO; o++) { e[o] = __expf(logits[o] - mx); sum += e[o]; }
        float inv = 1.0f / sum;
#pragma unroll
        for (int o = 0; o < NO; o++) out[b * NO + o] = e[o] * inv;
    }
}

// =====================================================================
extern "C" void kernel_launch(void* const* d_in, const int* in_sizes, int n_in,
                              void* d_out, int out_size) {
    const int*   inputs = (const int*)d_in[0];
    const float* emb = (const float*)d_in[1];
    const float* Wxr = (const float*)d_in[2];
    const float* Whr = (const float*)d_in[3];
    const float* br  = (const float*)d_in[4];
    const float* Wxz = (const float*)d_in[5];
    const float* Whz = (const float*)d_in[6];
    const float* bz  = (const float*)d_in[7];
    const float* Wxc = (const float*)d_in[8];
    const float* Whc = (const float*)d_in[9];
    const float* bc  = (const float*)d_in[10];
    const float* Whq = (const float*)d_in[11];
    const float* bq  = (const float*)d_in[12];
    float* out = (float*)d_out;

    static int smem_set = 0;
    if (!smem_set) {
        cudaFuncSetAttribute(gru_kernel,
                             cudaFuncAttributeMaxDynamicSharedMemorySize, GRU_SMEM);
        smem_set = 1;
    }

    reset_kernel<<<1, 256>>>();
    dim3 pg(48, 512);
    proj_kernel<<<pg, 256>>>(inputs, emb, Wxr, Wxz, Wxc, br, bz, bc);
    gru_kernel<<<NBLK, GTHR, GRU_SMEM>>>(Whr, Whz, Whc);
    out_kernel<<<64, 256>>>(Whq, bq, out);
}

// round 13
// speedup vs baseline: 1.1210x; 1.0719x over previous
#include <cuda_runtime.h>
#include <cuda_bf16.h>

#define BB 64
#define SS 512
#define EE 512
#define HD 1024
#define NO 10
#define NBLK 128
#define GTHR 512

typedef unsigned long long ull;

// -------- scratch --------
__device__ float g_xproj[(size_t)SS * BB * 3 * HD]; // [s][b][3072]
__device__ float g_H[2][HD * BB];                   // k-major [k][b]
__device__ float g_Hr[2][HD * BB];                  // double-buffered by step parity
__device__ unsigned g_arrive[NBLK * 32];
__device__ unsigned g_F1[NBLK * 32];
__device__ unsigned g_F2[NBLK * 32];
__device__ __nv_bfloat16 g_wt[3][2][HD][EE];        // [gate][hi/lo][n][k] transposed

// -------- packed f32x2 helpers --------
__device__ __forceinline__ ull ffma2(ull a, ull b, ull c) {
    ull d; asm("fma.rn.f32x2 %0, %1, %2, %3;" : "=l"(d) : "l"(a), "l"(b), "l"(c));
    return d;
}
__device__ __forceinline__ ull splat2(float x) {
    ull r; asm("mov.b64 %0, {%1,%1};" : "=l"(r) : "f"(x)); return r;
}
__device__ __forceinline__ float2 unpack2(ull v) {
    float2 f; asm("mov.b64 {%0,%1}, %2;" : "=f"(f.x), "=f"(f.y) : "l"(v)); return f;
}
__device__ __forceinline__ void ldcg_2x64(const float* p, ull& a, ull& b) {
    asm("ld.global.cg.v2.u64 {%0,%1}, [%2];" : "=l"(a), "=l"(b) : "l"(p));
}
__device__ __forceinline__ float2 ldcg_f2(const float* p) {
    float2 v; asm("ld.global.cg.v2.f32 {%0,%1}, [%2];" : "=f"(v.x), "=f"(v.y) : "l"(p));
    return v;
}
__device__ __forceinline__ float sigmoid_f(float x) {
    return 1.0f / (1.0f + __expf(-x));
}
__device__ __forceinline__ float tanh_f(float x) {
    float ax = fabsf(x);
    float t = __expf(-2.0f * ax);
    float r = __fdividef(1.0f - t, 1.0f + t);
    return copysignf(r, x);
}

// -------- mma helpers --------
__device__ __forceinline__ void ldsm_x4(unsigned& r0, unsigned& r1, unsigned& r2,
                                        unsigned& r3, unsigned addr) {
    asm volatile("ldmatrix.sync.aligned.m8n8.x4.shared.b16 {%0,%1,%2,%3}, [%4];"
                 : "=r"(r0), "=r"(r1), "=r"(r2), "=r"(r3) : "r"(addr));
}
__device__ __forceinline__ void mma_bf16(float* c, const unsigned* a,
                                         unsigned b0, unsigned b1) {
    asm volatile(
        "mma.sync.aligned.m16n8k16.row.col.f32.bf16.bf16.f32 "
        "{%0,%1,%2,%3},{%4,%5,%6,%7},{%8,%9},{%0,%1,%2,%3};"
        : "+f"(c[0]), "+f"(c[1]), "+f"(c[2]), "+f"(c[3])
        : "r"(a[0]), "r"(a[1]), "r"(a[2]), "r"(a[3]), "r"(b0), "r"(b1));
}

// -------- sync helpers --------
__device__ __forceinline__ void warp_wait_flags(const unsigned* F, int ks,
                                                unsigned target, int lane) {
    if (lane < 8) {
        const unsigned* p = F + (ks * 8 + lane) * 32;
        unsigned v;
        for (;;) {
            asm volatile("ld.relaxed.gpu.u32 %0, [%1];" : "=r"(v) : "l"(p) : "memory");
            if (v >= target) break;
            __nanosleep(20);
        }
        asm volatile("ld.acquire.gpu.u32 %0, [%1];" : "=r"(v) : "l"(p) : "memory");
    }
    __syncwarp();
}
__device__ __forceinline__ void publish(unsigned* slot, unsigned val) {
    asm volatile("st.release.gpu.u32 [%0], %1;" :: "l"(slot), "r"(val) : "memory");
}
__device__ __forceinline__ void flat_barrier(unsigned target, int bx) {
    __syncthreads();
    if (threadIdx.x == 0) {
        __threadfence();
        publish(&g_arrive[bx * 32], target);
    }
    if (threadIdx.x < NBLK) {
        const unsigned* p = &g_arrive[threadIdx.x * 32];
        unsigned v;
        do {
            asm volatile("ld.acquire.gpu.u32 %0, [%1];" : "=r"(v) : "l"(p) : "memory");
        } while (v < target);
    }
    __syncthreads();
}

__global__ void reset_kernel() {
    int t = threadIdx.x;
    for (int i = t; i < NBLK * 32; i += blockDim.x) {
        g_arrive[i] = 0u; g_F1[i] = 0u; g_F2[i] = 0u;
    }
}

// =====================================================================
// Kernel 0: weight convert fp32 -> transposed bf16 hi/lo  [gate][h][n][k]
// =====================================================================
__global__ __launch_bounds__(256) void wconv_kernel(
    const float* __restrict__ Wxr, const float* __restrict__ Wxz,
    const float* __restrict__ Wxc) {
    const int k = blockIdx.x;
    const int gate = blockIdx.y;
    const float* W = (gate == 0) ? Wxr : ((gate == 1) ? Wxz : Wxc);
    const int n0 = threadIdx.x * 4;
    float4 v = *(const float4*)(W + (size_t)k * HD + n0);
    float xs[4] = {v.x, v.y, v.z, v.w};
#pragma unroll
    for (int i = 0; i < 4; i++) {
        __nv_bfloat16 h = __float2bfloat16_rn(xs[i]);
        __nv_bfloat16 l = __float2bfloat16_rn(xs[i] - __bfloat162float(h));
        g_wt[gate][0][n0 + i][k] = h;
        g_wt[gate][1][n0 + i][k] = l;
    }
}

// =====================================================================
// Kernel 1: input projection via split-bf16 mma.sync (m16n8k16).
// grid (48, 512). 8 warps: warp tile 16m x 32n. 8 k-chunks of 64.
// FIXED: B staging covers full 64-k rows (4 x uint4 = 32 bf16 per thread).
// =====================================================================
__global__ __launch_bounds__(256) void proj_kernel(
    const int* __restrict__ inputs, const float* __restrict__ emb,
    const float* __restrict__ br, const float* __restrict__ bz,
    const float* __restrict__ bc) {
    __shared__ __align__(16) __nv_bfloat16 Ahi[64][72], Alo[64][72];
    __shared__ __align__(16) __nv_bfloat16 Bhi[64][72], Blo[64][72];
    __shared__ int tok[64];

    const int s  = blockIdx.y;
    const int nt = blockIdx.x;
    const int gate = nt >> 4;
    const int gc0  = (nt & 15) * 64;  // gate-local col base
    const float* bias = (gate == 0) ? br : ((gate == 1) ? bz : bc);

    const int tid = threadIdx.x;
    const int w = tid >> 5, lane = tid & 31;
    const int m0w = (w & 3) * 16;     // warp m base
    const int n0w = (w >> 2) * 32;    // warp n base

    if (tid < 64) tok[tid] = inputs[tid * SS + s];
    __syncthreads();

    // staging maps
    const int am = tid >> 2, akq = (tid & 3) * 16;          // A: 16 k/thread
    const int bh = tid >> 7, bn = (tid & 127) >> 1, bkq = (tid & 1) * 32;
    const float* arow = emb + (size_t)tok[am] * EE + akq;
    const __nv_bfloat16* bsrc = &g_wt[gate][bh][gc0 + bn][0] + bkq;

    // ldmatrix base addresses (lane-dependent)
    unsigned a_hi_base = (unsigned)__cvta_generic_to_shared(
        &Ahi[m0w + (lane & 7) + ((lane >> 3) & 1) * 8][((lane >> 4) & 1) * 8]);
    unsigned a_lo_base = (unsigned)__cvta_generic_to_shared(
        &Alo[m0w + (lane & 7) + ((lane >> 3) & 1) * 8][((lane >> 4) & 1) * 8]);
    const int brow = ((lane >> 4) & 1) * 8 + (lane & 7);
    const int bcol = ((lane >> 3) & 1) * 8;
    unsigned b_hi_base0 = (unsigned)__cvta_generic_to_shared(&Bhi[n0w + brow][bcol]);
    unsigned b_hi_base1 = (unsigned)__cvta_generic_to_shared(&Bhi[n0w + 16 + brow][bcol]);
    unsigned b_lo_base0 = (unsigned)__cvta_generic_to_shared(&Blo[n0w + brow][bcol]);
    unsigned b_lo_base1 = (unsigned)__cvta_generic_to_shared(&Blo[n0w + 16 + brow][bcol]);

    float acc[4][4];
#pragma unroll
    for (int a = 0; a < 4; a++)
#pragma unroll
        for (int i = 0; i < 4; i++) acc[a][i] = 0.f;

    // preload chunk 0
    float a_reg[16];
    uint4 b_reg[4];
    {
        *(float4*)(a_reg + 0)  = *(const float4*)(arow + 0);
        *(float4*)(a_reg + 4)  = *(const float4*)(arow + 4);
        *(float4*)(a_reg + 8)  = *(const float4*)(arow + 8);
        *(float4*)(a_reg + 12) = *(const float4*)(arow + 12);
        b_reg[0] = *(const uint4*)(bsrc);
        b_reg[1] = *(const uint4*)(bsrc + 8);
        b_reg[2] = *(const uint4*)(bsrc + 16);
        b_reg[3] = *(const uint4*)(bsrc + 24);
    }

#pragma unroll 1
    for (int c = 0; c < 8; ++c) {
        // STS chunk c
#pragma unroll
        for (int i = 0; i < 16; i += 2) {
            float x0 = a_reg[i], x1 = a_reg[i + 1];
            __nv_bfloat16 h0 = __float2bfloat16_rn(x0);
            __nv_bfloat16 h1 = __float2bfloat16_rn(x1);
            __nv_bfloat16 l0 = __float2bfloat16_rn(x0 - __bfloat162float(h0));
            __nv_bfloat16 l1 = __float2bfloat16_rn(x1 - __bfloat162float(h1));
            __nv_bfloat162 hv; hv.x = h0; hv.y = h1;
            __nv_bfloat162 lv; lv.x = l0; lv.y = l1;
            *(__nv_bfloat162*)&Ahi[am][akq + i] = hv;
            *(__nv_bfloat162*)&Alo[am][akq + i] = lv;
        }
        {
            __nv_bfloat16 (*Bd)[72] = bh ? Blo : Bhi;
            *(uint4*)&Bd[bn][bkq]      = b_reg[0];
            *(uint4*)&Bd[bn][bkq + 8]  = b_reg[1];
            *(uint4*)&Bd[bn][bkq + 16] = b_reg[2];
            *(uint4*)&Bd[bn][bkq + 24] = b_reg[3];
        }
        __syncthreads();
        // prefetch chunk c+1
        if (c < 7) {
            const float* an = arow + (c + 1) * 64;
            *(float4*)(a_reg + 0)  = *(const float4*)(an + 0);
            *(float4*)(a_reg + 4)  = *(const float4*)(an + 4);
            *(float4*)(a_reg + 8)  = *(const float4*)(an + 8);
            *(float4*)(a_reg + 12) = *(const float4*)(an + 12);
            const __nv_bfloat16* bnp = bsrc + (c + 1) * 64;
            b_reg[0] = *(const uint4*)(bnp);
            b_reg[1] = *(const uint4*)(bnp + 8);
            b_reg[2] = *(const uint4*)(bnp + 16);
            b_reg[3] = *(const uint4*)(bnp + 24);
        }
        // mma over 4 k16 steps
#pragma unroll
        for (int ks = 0; ks < 4; ++ks) {
            const unsigned off = ks * 32;  // 16 bf16 = 32 bytes
            unsigned ah[4], al[4], bh0[4], bh1[4], bl0[4], bl1[4];
            ldsm_x4(ah[0], ah[1], ah[2], ah[3], a_hi_base + off);
            ldsm_x4(al[0], al[1], al[2], al[3], a_lo_base + off);
            ldsm_x4(bh0[0], bh0[1], bh0[2], bh0[3], b_hi_base0 + off);
            ldsm_x4(bh1[0], bh1[1], bh1[2], bh1[3], b_hi_base1 + off);
            ldsm_x4(bl0[0], bl0[1], bl0[2], bl0[3], b_lo_base0 + off);
            ldsm_x4(bl1[0], bl1[1], bl1[2], bl1[3], b_lo_base1 + off);
            mma_bf16(acc[0], ah, bh0[0], bh0[1]);
            mma_bf16(acc[0], ah, bl0[0], bl0[1]);
            mma_bf16(acc[0], al, bh0[0], bh0[1]);
            mma_bf16(acc[1], ah, bh0[2], bh0[3]);
            mma_bf16(acc[1], ah, bl0[2], bl0[3]);
            mma_bf16(acc[1], al, bh0[2], bh0[3]);
            mma_bf16(acc[2], ah, bh1[0], bh1[1]);
            mma_bf16(acc[2], ah, bl1[0], bl1[1]);
            mma_bf16(acc[2], al, bh1[0], bh1[1]);
            mma_bf16(acc[3], ah, bh1[2], bh1[3]);
            mma_bf16(acc[3], ah, bl1[2], bl1[3]);
            mma_bf16(acc[3], al, bh1[2], bh1[3]);
        }
        __syncthreads();
    }

    // epilogue: add bias, store
    const int row0 = m0w + (lane >> 2);
#pragma unroll
    for (int a = 0; a < 4; a++) {
        const int col = gc0 + n0w + a * 8 + 2 * (lane & 3);  // gate-local
        float2 bi = *(const float2*)(bias + col);
        float2 v0 = make_float2(acc[a][0] + bi.x, acc[a][1] + bi.y);
        float2 v1 = make_float2(acc[a][2] + bi.x, acc[a][3] + bi.y);
        float* base = g_xproj + ((size_t)s * BB + row0) * (3 * HD) + gate * HD + col;
        __stcs((float2*)base, v0);
        __stcs((float2*)(base + 8 * 3 * HD), v1);
    }
}

// =====================================================================
// Kernel 2: persistent GRU (R11, unchanged)
// =====================================================================
#define RED_F   (16 * 512 * 2)
#define XP1_F   (64 * 18)
#define XP2_F   (64 * 10)
#define ZS_F    (8 * 64)
#define GRU_SMEM ((RED_F + XP1_F + XP2_F + ZS_F) * 4)

__global__ __launch_bounds__(GTHR, 1) void gru_kernel(
    const float* __restrict__ Whr, const float* __restrict__ Whz,
    const float* __restrict__ Whc) {
    extern __shared__ __align__(16) float smf[];
    ull*   red = (ull*)smf;
    float* xp1 = smf + RED_F;
    float* xp2 = smf + RED_F + XP1_F;
    float* zs  = smf + RED_F + XP1_F + XP2_F;

    const int tid = threadIdx.x, bx = blockIdx.x;
    const int w = tid >> 5, lane = tid & 31;
    const int mg = lane & 7;
    const int cg = lane >> 3;

    {
        int idx = bx * GTHR + tid;
        if (idx < HD * BB / 4)
            ((float4*)g_H[0])[idx] = make_float4(0.f, 0.f, 0.f, 0.f);
    }
    flat_barrier(1, bx);

    const int colb = bx * 8;
    const float* W1base = (cg < 2) ? Whr : Whz;
    const int w1col = colb + (cg & 1) * 4;

    const int e_el = tid & 31, e_q = tid >> 5;
    const int e1_i = e_q >> 2, e1_j = e_q & 3;
    const int e1_row = (e_el & 7) * 4 + e1_i;
    const int e1_col = (e_el >> 3) * 4 + e1_j;
    const int e1_mb = 2 * e1_row;
    const int e2_i = e_q >> 1, e2_j = e_q & 1;
    const int e2_row = (e_el & 7) * 4 + e2_i;
    const int e2_col = (e_el >> 3) * 2 + e2_j;
    const int e2_mb = 2 * e2_row;

    int p = 0;
#pragma unroll 1
    for (int s = 0; s < SS; ++s) {
        const float* Hc = g_H[p];
        float* Hn = g_H[p ^ 1];
        float* Hrbuf = g_Hr[s & 1];
        const float* xpg = g_xproj + (size_t)s * BB * 3 * HD;

        float2 xv1, xv2;
        {
            int b = tid >> 3, c2 = (tid & 7) * 2;
            const float* src = (c2 < 8)
                ? xpg + b * 3 * HD + 0 * HD + colb + c2
                : xpg + b * 3 * HD + 1 * HD + colb + (c2 - 8);
            xv1 = __ldcs((const float2*)src);
        }
        if (tid < 256) {
            int b = tid >> 2, q = tid & 3;
            xv2 = __ldcs((const float2*)(xpg + b * 3 * HD + 2 * HD + colb + q * 2));
        }
        float2 hc1, hc2;
        if (e1_col < 8) hc1 = ldcg_f2(Hc + (colb + e1_col) * BB + e1_mb);
        if (tid < 256)  hc2 = ldcg_f2(Hc + (colb + e2_col) * BB + e2_mb);

        warp_wait_flags(g_F2, w, (unsigned)s, lane);

        ull acc[4][4];
#pragma unroll
        for (int i = 0; i < 4; i++)
#pragma unroll
            for (int j = 0; j < 4; j++) acc[i][j] = 0ull;
        {
            const float* hptr = Hc + (w * 64) * BB + mg * 8;
            const float* wptr = W1base + (size_t)(w * 64) * HD + w1col;
#pragma unroll 1
            for (int k = 0; k < 64; k += 8) {
#pragma unroll
                for (int u = 0; u < 8; ++u) {
                    ull h0, h1, h2, h3;
                    ldcg_2x64(hptr, h0, h1);
                    ldcg_2x64(hptr + 4, h2, h3);
                    float4 wv = __ldg((const float4*)wptr);
                    ull w0 = splat2(wv.x), w1 = splat2(wv.y);
                    ull w2 = splat2(wv.z), w3 = splat2(wv.w);
                    acc[0][0] = ffma2(h0, w0, acc[0][0]);
                    acc[0][1] = ffma2(h0, w1, acc[0][1]);
                    acc[0][2] = ffma2(h0, w2, acc[0][2]);
                    acc[0][3] = ffma2(h0, w3, acc[0][3]);
                    acc[1][0] = ffma2(h1, w0, acc[1][0]);
                    acc[1][1] = ffma2(h1, w1, acc[1][1]);
                    acc[1][2] = ffma2(h1, w2, acc[1][2]);
                    acc[1][3] = ffma2(h1, w3, acc[1][3]);
                    acc[2][0] = ffma2(h2, w0, acc[2][0]);
                    acc[2][1] = ffma2(h2, w1, acc[2][1]);
                    acc[2][2] = ffma2(h2, w2, acc[2][2]);
                    acc[2][3] = ffma2(h2, w3, acc[2][3]);
                    acc[3][0] = ffma2(h3, w0, acc[3][0]);
                    acc[3][1] = ffma2(h3, w1, acc[3][1]);
                    acc[3][2] = ffma2(h3, w2, acc[3][2]);
                    acc[3][3] = ffma2(h3, w3, acc[3][3]);
                    hptr += BB; wptr += HD;
                }
            }
        }
#pragma unroll
        for (int i = 0; i < 4; i++)
#pragma unroll
            for (int j = 0; j < 4; j++)
                red[w * 512 + (i * 4 + j) * 32 + lane] = acc[i][j];
        {
            int b = tid >> 3, c2 = (tid & 7) * 2;
            *(float2*)&xp1[b * 18 + c2] = xv1;
        }
        if (tid < 256) {
            int b = tid >> 2, q = tid & 3;
            *(float2*)&xp2[b * 10 + q * 2] = xv2;
        }
        __syncthreads();

        {
            float2 sum = make_float2(0.f, 0.f);
#pragma unroll
            for (int ww = 0; ww < 16; ++ww) {
                float2 v = unpack2(red[ww * 512 + tid]);
                sum.x += v.x; sum.y += v.y;
            }
            float v0 = sigmoid_f(sum.x + xp1[e1_mb * 18 + e1_col]);
            float v1 = sigmoid_f(sum.y + xp1[(e1_mb + 1) * 18 + e1_col]);
            if (e1_col < 8) {
                *(float2*)(Hrbuf + (colb + e1_col) * BB + e1_mb) =
                    make_float2(hc1.x * v0, hc1.y * v1);
            } else {
                *(float2*)&zs[(e1_col - 8) * 64 + e1_mb] = make_float2(v0, v1);
            }
        }
        __syncthreads();
        if (tid == 0) {
            __threadfence();
            publish(&g_F1[bx * 32], (unsigned)(s + 1));
        }

        warp_wait_flags(g_F1, w, (unsigned)(s + 1), lane);

        ull acc2[4][2];
#pragma unroll
        for (int i = 0; i < 4; i++) { acc2[i][0] = 0ull; acc2[i][1] = 0ull; }
        {
            const float* hptr = Hrbuf + (w * 64) * BB + mg * 8;
            const float* wptr = Whc + (size_t)(w * 64) * HD + colb + cg * 2;
#pragma unroll 1
            for (int k = 0; k < 64; k += 8) {
#pragma unroll
                for (int u = 0; u < 8; ++u) {
                    ull h0, h1, h2, h3;
                    ldcg_2x64(hptr, h0, h1);
                    ldcg_2x64(hptr + 4, h2, h3);
                    float2 wv = __ldg((const float2*)wptr);
                    ull w0 = splat2(wv.x), w1 = splat2(wv.y);
                    acc2[0][0] = ffma2(h0, w0, acc2[0][0]);
                    acc2[0][1] = ffma2(h0, w1, acc2[0][1]);
                    acc2[1][0] = ffma2(h1, w0, acc2[1][0]);
                    acc2[1][1] = ffma2(h1, w1, acc2[1][1]);
                    acc2[2][0] = ffma2(h2, w0, acc2[2][0]);
                    acc2[2][1] = ffma2(h2, w1, acc2[2][1]);
                    acc2[3][0] = ffma2(h3, w0, acc2[3][0]);
                    acc2[3][1] = ffma2(h3, w1, acc2[3][1]);
                    hptr += BB; wptr += HD;
                }
            }
        }
#pragma unroll
        for (int i = 0; i < 4; i++)
#pragma unroll
            for (int j = 0; j < 2; j++)
                red[w * 512 + (i * 2 + j) * 32 + lane] = acc2[i][j];
        __syncthreads();

        if (tid < 256) {
            float2 sum = make_float2(0.f, 0.f);
#pragma unroll
            for (int ww = 0; ww < 16; ++ww) {
                float2 v = unpack2(red[ww * 512 + tid]);
                sum.x += v.x; sum.y += v.y;
            }
            float h0 = tanh_f(sum.x + xp2[e2_mb * 10 + e2_col]);
            float h1 = tanh_f(sum.y + xp2[(e2_mb + 1) * 10 + e2_col]);
            float2 z = *(const float2*)&zs[e2_col * 64 + e2_mb];
            *(float2*)(Hn + (colb + e2_col) * BB + e2_mb) =
                make_float2(z.x * hc2.x + (1.f - z.x) * h0,
                            z.y * hc2.y + (1.f - z.y) * h1);
        }
        __syncthreads();
        if (tid == 0) {
            __threadfence();
            publish(&g_F2[bx * 32], (unsigned)(s + 1));
        }
        p ^= 1;
    }
}

// =====================================================================
// Kernel 3: logits + softmax
// =====================================================================
__global__ __launch_bounds__(256) void out_kernel(const float* __restrict__ Whq,
                                                  const float* __restrict__ bq,
                                                  float* __restrict__ out) {
    const int b = blockIdx.x;
    const int t = threadIdx.x;
    float acc[NO];
#pragma unroll
    for (int o = 0; o < NO; o++) acc[o] = 0.f;
#pragma unroll
    for (int i = 0; i < HD / 256; i++) {
        int k = t + i * 256;
        float hv = g_H[0][k * BB + b];
        const float* wp = Whq + (size_t)k * NO;
#pragma unroll
        for (int o = 0; o < NO; o++) acc[o] += hv * wp[o];
    }
    __shared__ float part[256 * NO];
#pragma unroll
    for (int o = 0; o < NO; o++) part[t * NO + o] = acc[o];
    __syncthreads();
    __shared__ float logits[NO];
    if (t < NO) {
        float sum = bq[t];
        for (int i = 0; i < 256; i++) sum += part[i * NO + t];
        logits[t] = sum;
    }
    __syncthreads();
    if (t == 0) {
        float mx = logits[0];
#pragma unroll
        for (int o = 1; o < NO; o++) mx = fmaxf(mx, logits[o]);
        float e[NO]; float sum = 0.f;
#pragma unroll
        for (int o = 0; o < NO; o++) { e[o] = __expf(logits[o] - mx); sum += e[o]; }
        float inv = 1.0f / sum;
#pragma unroll
        for (int o = 0; o < NO; o++) out[b * NO + o] = e[o] * inv;
    }
}

// =====================================================================
extern "C" void kernel_launch(void* const* d_in, const int* in_sizes, int n_in,
                              void* d_out, int out_size) {
    const int*   inputs = (const int*)d_in[0];
    const float* emb = (const float*)d_in[1];
    const float* Wxr = (const float*)d_in[2];
    const float* Whr = (const float*)d_in[3];
    const float* br  = (const float*)d_in[4];
    const float* Wxz = (const float*)d_in[5];
    const float* Whz = (const float*)d_in[6];
    const float* bz  = (const float*)d_in[7];
    const float* Wxc = (const float*)d_in[8];
    const float* Whc = (const float*)d_in[9];
    const float* bc  = (const float*)d_in[10];
    const float* Whq = (const float*)d_in[11];
    const float* bq  = (const float*)d_in[12];
    float* out = (float*)d_out;

    static int smem_set = 0;
    if (!smem_set) {
        cudaFuncSetAttribute(gru_kernel,
                             cudaFuncAttributeMaxDynamicSharedMemorySize, GRU_SMEM);
        smem_set = 1;
    }

    reset_kernel<<<1, 256>>>();
    dim3 wg(512, 3);
    wconv_kernel<<<wg, 256>>>(Wxr, Wxz, Wxc);
    dim3 pg(48, 512);
    proj_kernel<<<pg, 256>>>(inputs, emb, br, bz, bc);
    gru_kernel<<<NBLK, GTHR, GRU_SMEM>>>(Whr, Whz, Whc);
    out_kernel<<<64, 256>>>(Whq, bq, out);
}

// round 14
// speedup vs baseline: 1.1262x; 1.0047x over previous
#include <cuda_runtime.h>
#include <cuda_bf16.h>

#define BB 64
#define SS 512
#define EE 512
#define HD 1024
#define NO 10
#define NBLK 128
#define GTHR 512

typedef unsigned long long ull;

// -------- scratch --------
__device__ float g_xproj[(size_t)SS * BB * 3 * HD]; // [s][b][3072]
__device__ float g_H[2][HD * BB];                   // k-major [k][b]
__device__ float g_Hr[2][HD * BB];                  // double-buffered by step parity
__device__ unsigned g_arrive[NBLK * 32];
__device__ unsigned g_F1[NBLK * 32];
__device__ unsigned g_F2[NBLK * 32];
__device__ __nv_bfloat16 g_wt[3][2][HD][EE];        // [gate][hi/lo][n][k] transposed

// -------- packed f32x2 helpers --------
__device__ __forceinline__ ull ffma2(ull a, ull b, ull c) {
    ull d; asm("fma.rn.f32x2 %0, %1, %2, %3;" : "=l"(d) : "l"(a), "l"(b), "l"(c));
    return d;
}
__device__ __forceinline__ ull splat2(float x) {
    ull r; asm("mov.b64 %0, {%1,%1};" : "=l"(r) : "f"(x)); return r;
}
__device__ __forceinline__ float2 unpack2(ull v) {
    float2 f; asm("mov.b64 {%0,%1}, %2;" : "=f"(f.x), "=f"(f.y) : "l"(v)); return f;
}
__device__ __forceinline__ void ldcg_2x64(const float* p, ull& a, ull& b) {
    asm("ld.global.cg.v2.u64 {%0,%1}, [%2];" : "=l"(a), "=l"(b) : "l"(p));
}
__device__ __forceinline__ float2 ldcg_f2(const float* p) {
    float2 v; asm("ld.global.cg.v2.f32 {%0,%1}, [%2];" : "=f"(v.x), "=f"(v.y) : "l"(p));
    return v;
}
__device__ __forceinline__ float sigmoid_f(float x) {
    return 1.0f / (1.0f + __expf(-x));
}
__device__ __forceinline__ float tanh_f(float x) {
    float ax = fabsf(x);
    float t = __expf(-2.0f * ax);
    float r = __fdividef(1.0f - t, 1.0f + t);
    return copysignf(r, x);
}

// -------- mma helpers --------
__device__ __forceinline__ void ldsm_x4(unsigned& r0, unsigned& r1, unsigned& r2,
                                        unsigned& r3, unsigned addr) {
    asm volatile("ldmatrix.sync.aligned.m8n8.x4.shared.b16 {%0,%1,%2,%3}, [%4];"
                 : "=r"(r0), "=r"(r1), "=r"(r2), "=r"(r3) : "r"(addr));
}
__device__ __forceinline__ void mma_bf16(float* c, const unsigned* a,
                                         unsigned b0, unsigned b1) {
    asm volatile(
        "mma.sync.aligned.m16n8k16.row.col.f32.bf16.bf16.f32 "
        "{%0,%1,%2,%3},{%4,%5,%6,%7},{%8,%9},{%0,%1,%2,%3};"
        : "+f"(c[0]), "+f"(c[1]), "+f"(c[2]), "+f"(c[3])
        : "r"(a[0]), "r"(a[1]), "r"(a[2]), "r"(a[3]), "r"(b0), "r"(b1));
}

// -------- sync helpers --------
__device__ __forceinline__ void warp_wait_flags(const unsigned* F, int ks,
                                                unsigned target, int lane) {
    if (lane < 8) {
        const unsigned* p = F + (ks * 8 + lane) * 32;
        unsigned v;
        for (;;) {
            asm volatile("ld.relaxed.gpu.u32 %0, [%1];" : "=r"(v) : "l"(p) : "memory");
            if (v >= target) break;
            __nanosleep(20);
        }
        asm volatile("ld.acquire.gpu.u32 %0, [%1];" : "=r"(v) : "l"(p) : "memory");
    }
    __syncwarp();
}
__device__ __forceinline__ void publish(unsigned* slot, unsigned val) {
    asm volatile("st.release.gpu.u32 [%0], %1;" :: "l"(slot), "r"(val) : "memory");
}
__device__ __forceinline__ void flat_barrier(unsigned target, int bx) {
    __syncthreads();
    if (threadIdx.x == 0) {
        __threadfence();
        publish(&g_arrive[bx * 32], target);
    }
    if (threadIdx.x < NBLK) {
        const unsigned* p = &g_arrive[threadIdx.x * 32];
        unsigned v;
        do {
            asm volatile("ld.acquire.gpu.u32 %0, [%1];" : "=r"(v) : "l"(p) : "memory");
        } while (v < target);
    }
    __syncthreads();
}

__global__ void reset_kernel() {
    int t = threadIdx.x;
    for (int i = t; i < NBLK * 32; i += blockDim.x) {
        g_arrive[i] = 0u; g_F1[i] = 0u; g_F2[i] = 0u;
    }
}

// =====================================================================
// Kernel 0: weight convert fp32 -> transposed bf16 hi/lo  [gate][h][n][k]
// =====================================================================
__global__ __launch_bounds__(256) void wconv_kernel(
    const float* __restrict__ Wxr, const float* __restrict__ Wxz,
    const float* __restrict__ Wxc) {
    const int k = blockIdx.x;
    const int gate = blockIdx.y;
    const float* W = (gate == 0) ? Wxr : ((gate == 1) ? Wxz : Wxc);
    const int n0 = threadIdx.x * 4;
    float4 v = *(const float4*)(W + (size_t)k * HD + n0);
    float xs[4] = {v.x, v.y, v.z, v.w};
#pragma unroll
    for (int i = 0; i < 4; i++) {
        __nv_bfloat16 h = __float2bfloat16_rn(xs[i]);
        __nv_bfloat16 l = __float2bfloat16_rn(xs[i] - __bfloat162float(h));
        g_wt[gate][0][n0 + i][k] = h;
        g_wt[gate][1][n0 + i][k] = l;
    }
}

// =====================================================================
// Kernel 1: input projection via split-bf16 mma.sync (m16n8k16).
// grid (48, 512). 8 warps: warp tile 16m x 32n. 8 k-chunks of 64.
// FIXED: B staging covers full 64-k rows (4 x uint4 = 32 bf16 per thread).
// =====================================================================
__global__ __launch_bounds__(256) void proj_kernel(
    const int* __restrict__ inputs, const float* __restrict__ emb,
    const float* __restrict__ br, const float* __restrict__ bz,
    const float* __restrict__ bc) {
    __shared__ __align__(16) __nv_bfloat16 Ahi[64][72], Alo[64][72];
    __shared__ __align__(16) __nv_bfloat16 Bhi[64][72], Blo[64][72];
    __shared__ int tok[64];

    const int s  = blockIdx.y;
    const int nt = blockIdx.x;
    const int gate = nt >> 4;
    const int gc0  = (nt & 15) * 64;  // gate-local col base
    const float* bias = (gate == 0) ? br : ((gate == 1) ? bz : bc);

    const int tid = threadIdx.x;
    const int w = tid >> 5, lane = tid & 31;
    const int m0w = (w & 3) * 16;     // warp m base
    const int n0w = (w >> 2) * 32;    // warp n base

    if (tid < 64) tok[tid] = inputs[tid * SS + s];
    __syncthreads();

    // staging maps
    const int am = tid >> 2, akq = (tid & 3) * 16;          // A: 16 k/thread
    const int bh = tid >> 7, bn = (tid & 127) >> 1, bkq = (tid & 1) * 32;
    const float* arow = emb + (size_t)tok[am] * EE + akq;
    const __nv_bfloat16* bsrc = &g_wt[gate][bh][gc0 + bn][0] + bkq;

    // ldmatrix base addresses (lane-dependent)
    unsigned a_hi_base = (unsigned)__cvta_generic_to_shared(
        &Ahi[m0w + (lane & 7) + ((lane >> 3) & 1) * 8][((lane >> 4) & 1) * 8]);
    unsigned a_lo_base = (unsigned)__cvta_generic_to_shared(
        &Alo[m0w + (lane & 7) + ((lane >> 3) & 1) * 8][((lane >> 4) & 1) * 8]);
    const int brow = ((lane >> 4) & 1) * 8 + (lane & 7);
    const int bcol = ((lane >> 3) & 1) * 8;
    unsigned b_hi_base0 = (unsigned)__cvta_generic_to_shared(&Bhi[n0w + brow][bcol]);
    unsigned b_hi_base1 = (unsigned)__cvta_generic_to_shared(&Bhi[n0w + 16 + brow][bcol]);
    unsigned b_lo_base0 = (unsigned)__cvta_generic_to_shared(&Blo[n0w + brow][bcol]);
    unsigned b_lo_base1 = (unsigned)__cvta_generic_to_shared(&Blo[n0w + 16 + brow][bcol]);

    float acc[4][4];
#pragma unroll
    for (int a = 0; a < 4; a++)
#pragma unroll
        for (int i = 0; i < 4; i++) acc[a][i] = 0.f;

    // preload chunk 0
    float a_reg[16];
    uint4 b_reg[4];
    {
        *(float4*)(a_reg + 0)  = *(const float4*)(arow + 0);
        *(float4*)(a_reg + 4)  = *(const float4*)(arow + 4);
        *(float4*)(a_reg + 8)  = *(const float4*)(arow + 8);
        *(float4*)(a_reg + 12) = *(const float4*)(arow + 12);
        b_reg[0] = *(const uint4*)(bsrc);
        b_reg[1] = *(const uint4*)(bsrc + 8);
        b_reg[2] = *(const uint4*)(bsrc + 16);
        b_reg[3] = *(const uint4*)(bsrc + 24);
    }

#pragma unroll 1
    for (int c = 0; c < 8; ++c) {
        // STS chunk c
#pragma unroll
        for (int i = 0; i < 16; i += 2) {
            float x0 = a_reg[i], x1 = a_reg[i + 1];
            __nv_bfloat16 h0 = __float2bfloat16_rn(x0);
            __nv_bfloat16 h1 = __float2bfloat16_rn(x1);
            __nv_bfloat16 l0 = __float2bfloat16_rn(x0 - __bfloat162float(h0));
            __nv_bfloat16 l1 = __float2bfloat16_rn(x1 - __bfloat162float(h1));
            __nv_bfloat162 hv; hv.x = h0; hv.y = h1;
            __nv_bfloat162 lv; lv.x = l0; lv.y = l1;
            *(__nv_bfloat162*)&Ahi[am][akq + i] = hv;
            *(__nv_bfloat162*)&Alo[am][akq + i] = lv;
        }
        {
            __nv_bfloat16 (*Bd)[72] = bh ? Blo : Bhi;
            *(uint4*)&Bd[bn][bkq]      = b_reg[0];
            *(uint4*)&Bd[bn][bkq + 8]  = b_reg[1];
            *(uint4*)&Bd[bn][bkq + 16] = b_reg[2];
            *(uint4*)&Bd[bn][bkq + 24] = b_reg[3];
        }
        __syncthreads();
        // prefetch chunk c+1
        if (c < 7) {
            const float* an = arow + (c + 1) * 64;
            *(float4*)(a_reg + 0)  = *(const float4*)(an + 0);
            *(float4*)(a_reg + 4)  = *(const float4*)(an + 4);
            *(float4*)(a_reg + 8)  = *(const float4*)(an + 8);
            *(float4*)(a_reg + 12) = *(const float4*)(an + 12);
            const __nv_bfloat16* bnp = bsrc + (c + 1) * 64;
            b_reg[0] = *(const uint4*)(bnp);
            b_reg[1] = *(const uint4*)(bnp + 8);
            b_reg[2] = *(const uint4*)(bnp + 16);
            b_reg[3] = *(const uint4*)(bnp + 24);
        }
        // mma over 4 k16 steps
#pragma unroll
        for (int ks = 0; ks < 4; ++ks) {
            const unsigned off = ks * 32;  // 16 bf16 = 32 bytes
            unsigned ah[4], al[4], bh0[4], bh1[4], bl0[4], bl1[4];
            ldsm_x4(ah[0], ah[1], ah[2], ah[3], a_hi_base + off);
            ldsm_x4(al[0], al[1], al[2], al[3], a_lo_base + off);
            ldsm_x4(bh0[0], bh0[1], bh0[2], bh0[3], b_hi_base0 + off);
            ldsm_x4(bh1[0], bh1[1], bh1[2], bh1[3], b_hi_base1 + off);
            ldsm_x4(bl0[0], bl0[1], bl0[2], bl0[3], b_lo_base0 + off);
            ldsm_x4(bl1[0], bl1[1], bl1[2], bl1[3], b_lo_base1 + off);
            mma_bf16(acc[0], ah, bh0[0], bh0[1]);
            mma_bf16(acc[0], ah, bl0[0], bl0[1]);
            mma_bf16(acc[0], al, bh0[0], bh0[1]);
            mma_bf16(acc[1], ah, bh0[2], bh0[3]);
            mma_bf16(acc[1], ah, bl0[2], bl0[3]);
            mma_bf16(acc[1], al, bh0[2], bh0[3]);
            mma_bf16(acc[2], ah, bh1[0], bh1[1]);
            mma_bf16(acc[2], ah, bl1[0], bl1[1]);
            mma_bf16(acc[2], al, bh1[0], bh1[1]);
            mma_bf16(acc[3], ah, bh1[2], bh1[3]);
            mma_bf16(acc[3], ah, bl1[2], bl1[3]);
            mma_bf16(acc[3], al, bh1[2], bh1[3]);
        }
        __syncthreads();
    }

    // epilogue: add bias, store
    const int row0 = m0w + (lane >> 2);
#pragma unroll
    for (int a = 0; a < 4; a++) {
        const int col = gc0 + n0w + a * 8 + 2 * (lane & 3);  // gate-local
        float2 bi = *(const float2*)(bias + col);
        float2 v0 = make_float2(acc[a][0] + bi.x, acc[a][1] + bi.y);
        float2 v1 = make_float2(acc[a][2] + bi.x, acc[a][3] + bi.y);
        float* base = g_xproj + ((size_t)s * BB + row0) * (3 * HD) + gate * HD + col;
        __stcs((float2*)base, v0);
        __stcs((float2*)(base + 8 * 3 * HD), v1);
    }
}

// =====================================================================
// Kernel 2: persistent GRU (R11, unchanged)
// =====================================================================
#define RED_F   (16 * 512 * 2)
#define XP1_F   (64 * 18)
#define XP2_F   (64 * 10)
#define ZS_F    (8 * 64)
#define GRU_SMEM ((RED_F + XP1_F + XP2_F + ZS_F) * 4)

__global__ __launch_bounds__(GTHR, 1) void gru_kernel(
    const float* __restrict__ Whr, const float* __restrict__ Whz,
    const float* __restrict__ Whc) {
    extern __shared__ __align__(16) float smf[];
    ull*   red = (ull*)smf;
    float* xp1 = smf + RED_F;
    float* xp2 = smf + RED_F + XP1_F;
    float* zs  = smf + RED_F + XP1_F + XP2_F;

    const int tid = threadIdx.x, bx = blockIdx.x;
    const int w = tid >> 5, lane = tid & 31;
    const int mg = lane & 7;
    const int cg = lane >> 3;

    {
        int idx = bx * GTHR + tid;
        if (idx < HD * BB / 4)
            ((float4*)g_H[0])[idx] = make_float4(0.f, 0.f, 0.f, 0.f);
    }
    flat_barrier(1, bx);

    const int colb = bx * 8;
    const float* W1base = (cg < 2) ? Whr : Whz;
    const int w1col = colb + (cg & 1) * 4;

    const int e_el = tid & 31, e_q = tid >> 5;
    const int e1_i = e_q >> 2, e1_j = e_q & 3;
    const int e1_row = (e_el & 7) * 4 + e1_i;
    const int e1_col = (e_el >> 3) * 4 + e1_j;
    const int e1_mb = 2 * e1_row;
    const int e2_i = e_q >> 1, e2_j = e_q & 1;
    const int e2_row = (e_el & 7) * 4 + e2_i;
    const int e2_col = (e_el >> 3) * 2 + e2_j;
    const int e2_mb = 2 * e2_row;

    int p = 0;
#pragma unroll 1
    for (int s = 0; s < SS; ++s) {
        const float* Hc = g_H[p];
        float* Hn = g_H[p ^ 1];
        float* Hrbuf = g_Hr[s & 1];
        const float* xpg = g_xproj + (size_t)s * BB * 3 * HD;

        float2 xv1, xv2;
        {
            int b = tid >> 3, c2 = (tid & 7) * 2;
            const float* src = (c2 < 8)
                ? xpg + b * 3 * HD + 0 * HD + colb + c2
                : xpg + b * 3 * HD + 1 * HD + colb + (c2 - 8);
            xv1 = __ldcs((const float2*)src);
        }
        if (tid < 256) {
            int b = tid >> 2, q = tid & 3;
            xv2 = __ldcs((const float2*)(xpg + b * 3 * HD + 2 * HD + colb + q * 2));
        }
        float2 hc1, hc2;
        if (e1_col < 8) hc1 = ldcg_f2(Hc + (colb + e1_col) * BB + e1_mb);
        if (tid < 256)  hc2 = ldcg_f2(Hc + (colb + e2_col) * BB + e2_mb);

        warp_wait_flags(g_F2, w, (unsigned)s, lane);

        ull acc[4][4];
#pragma unroll
        for (int i = 0; i < 4; i++)
#pragma unroll
            for (int j = 0; j < 4; j++) acc[i][j] = 0ull;
        {
            const float* hptr = Hc + (w * 64) * BB + mg * 8;
            const float* wptr = W1base + (size_t)(w * 64) * HD + w1col;
#pragma unroll 1
            for (int k = 0; k < 64; k += 8) {
#pragma unroll
                for (int u = 0; u < 8; ++u) {
                    ull h0, h1, h2, h3;
                    ldcg_2x64(hptr, h0, h1);
                    ldcg_2x64(hptr + 4, h2, h3);
                    float4 wv = __ldg((const float4*)wptr);
                    ull w0 = splat2(wv.x), w1 = splat2(wv.y);
                    ull w2 = splat2(wv.z), w3 = splat2(wv.w);
                    acc[0][0] = ffma2(h0, w0, acc[0][0]);
                    acc[0][1] = ffma2(h0, w1, acc[0][1]);
                    acc[0][2] = ffma2(h0, w2, acc[0][2]);
                    acc[0][3] = ffma2(h0, w3, acc[0][3]);
                    acc[1][0] = ffma2(h1, w0, acc[1][0]);
                    acc[1][1] = ffma2(h1, w1, acc[1][1]);
                    acc[1][2] = ffma2(h1, w2, acc[1][2]);
                    acc[1][3] = ffma2(h1, w3, acc[1][3]);
                    acc[2][0] = ffma2(h2, w0, acc[2][0]);
                    acc[2][1] = ffma2(h2, w1, acc[2][1]);
                    acc[2][2] = ffma2(h2, w2, acc[2][2]);
                    acc[2][3] = ffma2(h2, w3, acc[2][3]);
                    acc[3][0] = ffma2(h3, w0, acc[3][0]);
                    acc[3][1] = ffma2(h3, w1, acc[3][1]);
                    acc[3][2] = ffma2(h3, w2, acc[3][2]);
                    acc[3][3] = ffma2(h3, w3, acc[3][3]);
                    hptr += BB; wptr += HD;
                }
            }
        }
#pragma unroll
        for (int i = 0; i < 4; i++)
#pragma unroll
            for (int j = 0; j < 4; j++)
                red[w * 512 + (i * 4 + j) * 32 + lane] = acc[i][j];
        {
            int b = tid >> 3, c2 = (tid & 7) * 2;
            *(float2*)&xp1[b * 18 + c2] = xv1;
        }
        if (tid < 256) {
            int b = tid >> 2, q = tid & 3;
            *(float2*)&xp2[b * 10 + q * 2] = xv2;
        }
        __syncthreads();

        {
            float2 sum = make_float2(0.f, 0.f);
#pragma unroll
            for (int ww = 0; ww < 16; ++ww) {
                float2 v = unpack2(red[ww * 512 + tid]);
                sum.x += v.x; sum.y += v.y;
            }
            float v0 = sigmoid_f(sum.x + xp1[e1_mb * 18 + e1_col]);
            float v1 = sigmoid_f(sum.y + xp1[(e1_mb + 1) * 18 + e1_col]);
            if (e1_col < 8) {
                *(float2*)(Hrbuf + (colb + e1_col) * BB + e1_mb) =
                    make_float2(hc1.x * v0, hc1.y * v1);
            } else {
                *(float2*)&zs[(e1_col - 8) * 64 + e1_mb] = make_float2(v0, v1);
            }
        }
        __syncthreads();
        if (tid == 0) {
            __threadfence();
            publish(&g_F1[bx * 32], (unsigned)(s + 1));
        }

        warp_wait_flags(g_F1, w, (unsigned)(s + 1), lane);

        ull acc2[4][2];
#pragma unroll
        for (int i = 0; i < 4; i++) { acc2[i][0] = 0ull; acc2[i][1] = 0ull; }
        {
            const float* hptr = Hrbuf + (w * 64) * BB + mg * 8;
            const float* wptr = Whc + (size_t)(w * 64) * HD + colb + cg * 2;
#pragma unroll 1
            for (int k = 0; k < 64; k += 8) {
#pragma unroll
                for (int u = 0; u < 8; ++u) {
                    ull h0, h1, h2, h3;
                    ldcg_2x64(hptr, h0, h1);
                    ldcg_2x64(hptr + 4, h2, h3);
                    float2 wv = __ldg((const float2*)wptr);
                    ull w0 = splat2(wv.x), w1 = splat2(wv.y);
                    acc2[0][0] = ffma2(h0, w0, acc2[0][0]);
                    acc2[0][1] = ffma2(h0, w1, acc2[0][1]);
                    acc2[1][0] = ffma2(h1, w0, acc2[1][0]);
                    acc2[1][1] = ffma2(h1, w1, acc2[1][1]);
                    acc2[2][0] = ffma2(h2, w0, acc2[2][0]);
                    acc2[2][1] = ffma2(h2, w1, acc2[2][1]);
                    acc2[3][0] = ffma2(h3, w0, acc2[3][0]);
                    acc2[3][1] = ffma2(h3, w1, acc2[3][1]);
                    hptr += BB; wptr += HD;
                }
            }
        }
#pragma unroll
        for (int i = 0; i < 4; i++)
#pragma unroll
            for (int j = 0; j < 2; j++)
                red[w * 512 + (i * 2 + j) * 32 + lane] = acc2[i][j];
        __syncthreads();

        if (tid < 256) {
            float2 sum = make_float2(0.f, 0.f);
#pragma unroll
            for (int ww = 0; ww < 16; ++ww) {
                float2 v = unpack2(red[ww * 512 + tid]);
                sum.x += v.x; sum.y += v.y;
            }
            float h0 = tanh_f(sum.x + xp2[e2_mb * 10 + e2_col]);
            float h1 = tanh_f(sum.y + xp2[(e2_mb + 1) * 10 + e2_col]);
            float2 z = *(const float2*)&zs[e2_col * 64 + e2_mb];
            *(float2*)(Hn + (colb + e2_col) * BB + e2_mb) =
                make_float2(z.x * hc2.x + (1.f - z.x) * h0,
                            z.y * hc2.y + (1.f - z.y) * h1);
        }
        __syncthreads();
        if (tid == 0) {
            __threadfence();
            publish(&g_F2[bx * 32], (unsigned)(s + 1));
        }
        p ^= 1;
    }
}

// =====================================================================
// Kernel 3: logits + softmax
// =====================================================================
__global__ __launch_bounds__(256) void out_kernel(const float* __restrict__ Whq,
                                                  const float* __restrict__ bq,
                                                  float* __restrict__ out) {
    const int b = blockIdx.x;
    const int t = threadIdx.x;
    float acc[NO];
#pragma unroll
    for (int o = 0; o < NO; o++) acc[o] = 0.f;
#pragma unroll
    for (int i = 0; i < HD / 256; i++) {
        int k = t + i * 256;
        float hv = g_H[0][k * BB + b];
        const float* wp = Whq + (size_t)k * NO;
#pragma unroll
        for (int o = 0; o < NO; o++) acc[o] += hv * wp[o];
    }
    __shared__ float part[256 * NO];
#pragma unroll
    for (int o = 0; o < NO; o++) part[t * NO + o] = acc[o];
    __syncthreads();
    __shared__ float logits[NO];
    if (t < NO) {
        float sum = bq[t];
        for (int i = 0; i < 256; i++) sum += part[i * NO + t];
        logits[t] = sum;
    }
    __syncthreads();
    if (t == 0) {
        float mx = logits[0];
#pragma unroll
        for (int o = 1; o < NO; o++) mx = fmaxf(mx, logits[o]);
        float e[NO]; float sum = 0.f;
#pragma unroll
        for (int o = 0; o < NO; o++) { e[o] = __expf(logits[o] - mx); sum += e[o]; }
        float inv = 1.0f / sum;
#pragma unroll
        for (int o = 0; o < NO; o++) out[b * NO + o] = e[o] * inv;
    }
}

// =====================================================================
extern "C" void kernel_launch(void* const* d_in, const int* in_sizes, int n_in,
                              void* d_out, int out_size) {
    const int*   inputs = (const int*)d_in[0];
    const float* emb = (const float*)d_in[1];
    const float* Wxr = (const float*)d_in[2];
    const float* Whr = (const float*)d_in[3];
    const float* br  = (const float*)d_in[4];
    const float* Wxz = (const float*)d_in[5];
    const float* Whz = (const float*)d_in[6];
    const float* bz  = (const float*)d_in[7];
    const float* Wxc = (const float*)d_in[8];
    const float* Whc = (const float*)d_in[9];
    const float* bc  = (const float*)d_in[10];
    const float* Whq = (const float*)d_in[11];
    const float* bq  = (const float*)d_in[12];
    float* out = (float*)d_out;

    static int smem_set = 0;
    if (!smem_set) {
        cudaFuncSetAttribute(gru_kernel,
                             cudaFuncAttributeMaxDynamicSharedMemorySize, GRU_SMEM);
        smem_set = 1;
    }

    reset_kernel<<<1, 256>>>();
    dim3 wg(512, 3);
    wconv_kernel<<<wg, 256>>>(Wxr, Wxz, Wxc);
    dim3 pg(48, 512);
    proj_kernel<<<pg, 256>>>(inputs, emb, br, bz, bc);
    gru_kernel<<<NBLK, GTHR, GRU_SMEM>>>(Whr, Whz, Whc);
    out_kernel<<<64, 256>>>(Whq, bq, out);
}